// round 4
// baseline (speedup 1.0000x reference)
#include <cuda_runtime.h>
#include <cstdint>

#define N_SRC 50000
#define N_DST 50000
#define IN_FEAT 128
#define OUT_FEAT 128
#define MAX_EDGES 600000

// ---------------------------------------------------------------------------
// Device-global scratch (allocation-free).
// ---------------------------------------------------------------------------
__device__ float g_neigh[(size_t)N_DST * IN_FEAT];  // mean-aggregated (1/deg folded in)
__device__ int   g_cnt[N_DST];
__device__ int   g_offs[N_DST + 1];
__device__ int   g_cursor[N_DST];
__device__ int   g_csr[MAX_EDGES];

// ---------------------------------------------------------------------------
// 1) zero the per-dst counters
// ---------------------------------------------------------------------------
__global__ void zero_cnt_kernel() {
    int i = blockIdx.x * blockDim.x + threadIdx.x;
    if (i < N_DST) g_cnt[i] = 0;
}

// ---------------------------------------------------------------------------
// 2) histogram of dst
// ---------------------------------------------------------------------------
__global__ __launch_bounds__(256) void hist_kernel(const int* __restrict__ dst, int n_edges) {
    int i = blockIdx.x * blockDim.x + threadIdx.x;
    if (i < n_edges) atomicAdd(&g_cnt[__ldg(dst + i)], 1);
}

// ---------------------------------------------------------------------------
// 3) exclusive scan (single block). Writes g_offs[0..N_DST] and g_cursor.
// ---------------------------------------------------------------------------
#define SCAN_THREADS 1024
__global__ __launch_bounds__(SCAN_THREADS) void scan_kernel() {
    __shared__ int part[SCAN_THREADS];
    const int t = threadIdx.x;
    const int CH = (N_DST + SCAN_THREADS - 1) / SCAN_THREADS;   // 49
    int beg = t * CH;
    int end = min(beg + CH, N_DST);
    int s = 0;
    for (int i = beg; i < end; ++i) s += g_cnt[i];
    part[t] = s;
    __syncthreads();
    // Hillis-Steele inclusive scan
    for (int off = 1; off < SCAN_THREADS; off <<= 1) {
        int v = (t >= off) ? part[t - off] : 0;
        __syncthreads();
        part[t] += v;
        __syncthreads();
    }
    int run = (t == 0) ? 0 : part[t - 1];
    for (int i = beg; i < end; ++i) {
        g_offs[i] = run;
        g_cursor[i] = run;
        run += g_cnt[i];
    }
    if (t == SCAN_THREADS - 1) g_offs[N_DST] = run;
}

// ---------------------------------------------------------------------------
// 4) scatter src ids into CSR buckets
// ---------------------------------------------------------------------------
__global__ __launch_bounds__(256) void scatter_kernel(
    const int* __restrict__ src, const int* __restrict__ dst, int n_edges)
{
    int i = blockIdx.x * blockDim.x + threadIdx.x;
    if (i < n_edges) {
        int d = __ldg(dst + i);
        int pos = atomicAdd(&g_cursor[d], 1);
        g_csr[pos] = __ldg(src + i);
    }
}

// ---------------------------------------------------------------------------
// 5) aggregation: one warp per dst, mean of gathered h_s rows.
// ---------------------------------------------------------------------------
__global__ __launch_bounds__(256) void agg_kernel(const float* __restrict__ h_s) {
    int w    = (blockIdx.x * blockDim.x + threadIdx.x) >> 5;
    int lane = threadIdx.x & 31;
    if (w >= N_DST) return;

    int beg = __ldg(g_offs + w);
    int end = __ldg(g_offs + w + 1);

    float4 acc = make_float4(0.f, 0.f, 0.f, 0.f);
    const float4* hs4 = reinterpret_cast<const float4*>(h_s);

    int e = beg;
    for (; e + 1 < end; e += 2) {
        int s0 = __ldg(g_csr + e);
        int s1 = __ldg(g_csr + e + 1);
        float4 v0 = __ldg(hs4 + (size_t)s0 * 32 + lane);
        float4 v1 = __ldg(hs4 + (size_t)s1 * 32 + lane);
        acc.x += v0.x + v1.x;
        acc.y += v0.y + v1.y;
        acc.z += v0.z + v1.z;
        acc.w += v0.w + v1.w;
    }
    if (e < end) {
        int s0 = __ldg(g_csr + e);
        float4 v0 = __ldg(hs4 + (size_t)s0 * 32 + lane);
        acc.x += v0.x; acc.y += v0.y; acc.z += v0.z; acc.w += v0.w;
    }

    float inv = 1.f / fmaxf((float)(end - beg), 1.f);
    acc.x *= inv; acc.y *= inv; acc.z *= inv; acc.w *= inv;
    reinterpret_cast<float4*>(g_neigh)[(size_t)w * 32 + lane] = acc;
}

// ---------------------------------------------------------------------------
// 6) fused concat + Linear via TF32 mma.sync, ldmatrix fragment loads.
//    out[d,o] = b[o] + sum_k h_d[d,k]*W[o,k] + g_neigh[d,k]*W[o,128+k]
// ---------------------------------------------------------------------------
#define BM 128
#define BK 32
#define KPAD 36   // row stride = 9x16B units -> distinct mod 8 for LDSM rows

__device__ __forceinline__ uint32_t f2tf32(float v) {
    uint32_t r;
    asm("cvt.rna.tf32.f32 %0, %1;" : "=r"(r) : "f"(v));
    return r;
}

__device__ __forceinline__ void mma_tf32(float c[4],
                                         uint32_t a0, uint32_t a1, uint32_t a2, uint32_t a3,
                                         uint32_t b0, uint32_t b1) {
    asm("mma.sync.aligned.m16n8k8.row.col.f32.tf32.tf32.f32 "
        "{%0,%1,%2,%3}, {%4,%5,%6,%7}, {%8,%9}, {%0,%1,%2,%3};"
        : "+f"(c[0]), "+f"(c[1]), "+f"(c[2]), "+f"(c[3])
        : "r"(a0), "r"(a1), "r"(a2), "r"(a3), "r"(b0), "r"(b1));
}

#define LDSM_X4(r0, r1, r2, r3, addr) \
    asm volatile("ldmatrix.sync.aligned.m8n8.x4.shared.b16 {%0,%1,%2,%3}, [%4];" \
                 : "=r"(r0), "=r"(r1), "=r"(r2), "=r"(r3) : "r"(addr))

__global__ __launch_bounds__(256) void gemm_kernel(
    const float* __restrict__ h_d,
    const float* __restrict__ W,     // [128, 256] row-major
    const float* __restrict__ bias,  // [128]
    float* __restrict__ out)         // [N_DST, 128]
{
    __shared__ uint32_t As[BM][KPAD];        // [m][k] tf32
    __shared__ uint32_t Bs[OUT_FEAT][KPAD];  // [n][k] tf32

    const int t    = threadIdx.x;
    const int bm   = blockIdx.x * BM;
    const int wid  = t >> 5;
    const int lane = t & 31;
    const int warp_m = wid >> 1;   // 0..3
    const int warp_n = wid & 1;    // 0..1
    const int group  = lane >> 2;  // 0..7
    const int tid4   = lane & 3;   // 0..3

    // ldmatrix per-thread row addresses
    const int lrow = lane & 7;
    const int lmat = lane >> 3;    // which 8x8 tile of the x4
    uint32_t as_base = (uint32_t)__cvta_generic_to_shared(&As[0][0]);
    uint32_t bs_base = (uint32_t)__cvta_generic_to_shared(&Bs[0][0]);

    uint32_t aAddr[2];
    #pragma unroll
    for (int mt = 0; mt < 2; ++mt) {
        int row = warp_m * 32 + mt * 16 + (lmat & 1) * 8 + lrow;
        int col = (lmat >> 1) * 4;
        aAddr[mt] = as_base + (row * KPAD + col) * 4;
    }
    uint32_t bAddr[4];
    #pragma unroll
    for (int p = 0; p < 4; ++p) {
        int row = warp_n * 64 + p * 16 + (lmat >> 1) * 8 + lrow;
        int col = (lmat & 1) * 4;
        bAddr[p] = bs_base + (row * KPAD + col) * 4;
    }

    float acc[2][8][4];
    #pragma unroll
    for (int mt = 0; mt < 2; ++mt)
        #pragma unroll
        for (int nt = 0; nt < 8; ++nt)
            #pragma unroll
            for (int c = 0; c < 4; ++c) acc[mt][nt][c] = 0.f;

    #pragma unroll 1
    for (int ph = 0; ph < 2; ++ph) {
        const float* __restrict__ A = ph ? g_neigh : h_d;
        #pragma unroll 1
        for (int k0 = 0; k0 < IN_FEAT; k0 += BK) {
            __syncthreads();

            // --- A tile: 128 rows x 32 cols
            #pragma unroll
            for (int i = 0; i < 4; ++i) {
                int idx = t + i * 256;          // 0..1023
                int row = idx >> 3;             // 0..127
                int c4  = (idx & 7) * 4;        // 0..28
                int gr  = bm + row;
                float4 v = make_float4(0.f, 0.f, 0.f, 0.f);
                if (gr < N_DST)
                    v = __ldg(reinterpret_cast<const float4*>(A + (size_t)gr * IN_FEAT + k0 + c4));
                As[row][c4 + 0] = f2tf32(v.x);
                As[row][c4 + 1] = f2tf32(v.y);
                As[row][c4 + 2] = f2tf32(v.z);
                As[row][c4 + 3] = f2tf32(v.w);
            }
            // --- B tile: Bs[o][k] = W[o][ph*128 + k0 + k]
            #pragma unroll
            for (int i = 0; i < 4; ++i) {
                int idx = t + i * 256;
                int o   = idx >> 3;
                int c4  = (idx & 7) * 4;
                float4 v = __ldg(reinterpret_cast<const float4*>(
                    W + (size_t)o * (2 * IN_FEAT) + ph * IN_FEAT + k0 + c4));
                Bs[o][c4 + 0] = f2tf32(v.x);
                Bs[o][c4 + 1] = f2tf32(v.y);
                Bs[o][c4 + 2] = f2tf32(v.z);
                Bs[o][c4 + 3] = f2tf32(v.w);
            }
            __syncthreads();

            // --- compute: 4 k8-steps
            #pragma unroll
            for (int kk = 0; kk < BK; kk += 8) {
                uint32_t af[2][4], bf[8][2];
                #pragma unroll
                for (int mt = 0; mt < 2; ++mt)
                    LDSM_X4(af[mt][0], af[mt][1], af[mt][2], af[mt][3],
                            aAddr[mt] + kk * 4);
                #pragma unroll
                for (int p = 0; p < 4; ++p)
                    LDSM_X4(bf[2 * p][0], bf[2 * p][1], bf[2 * p + 1][0], bf[2 * p + 1][1],
                            bAddr[p] + kk * 4);
                #pragma unroll
                for (int mt = 0; mt < 2; ++mt)
                    #pragma unroll
                    for (int nt = 0; nt < 8; ++nt)
                        mma_tf32(acc[mt][nt], af[mt][0], af[mt][1], af[mt][2], af[mt][3],
                                 bf[nt][0], bf[nt][1]);
            }
        }
    }

    // --- epilogue: bias + store
    #pragma unroll
    for (int mt = 0; mt < 2; ++mt) {
        int r0 = bm + warp_m * 32 + mt * 16 + group;
        #pragma unroll
        for (int nt = 0; nt < 8; ++nt) {
            int c = warp_n * 64 + nt * 8 + tid4 * 2;
            float b0 = __ldg(bias + c);
            float b1 = __ldg(bias + c + 1);
            if (r0 < N_DST) {
                float2 v = make_float2(acc[mt][nt][0] + b0, acc[mt][nt][1] + b1);
                *reinterpret_cast<float2*>(out + (size_t)r0 * OUT_FEAT + c) = v;
            }
            int r1 = r0 + 8;
            if (r1 < N_DST) {
                float2 v = make_float2(acc[mt][nt][2] + b0, acc[mt][nt][3] + b1);
                *reinterpret_cast<float2*>(out + (size_t)r1 * OUT_FEAT + c) = v;
            }
        }
    }
}

// ---------------------------------------------------------------------------
extern "C" void kernel_launch(void* const* d_in, const int* in_sizes, int n_in,
                              void* d_out, int out_size)
{
    const float* h_s = (const float*)d_in[0];
    const float* h_d = (const float*)d_in[1];
    const int*   src = (const int*)d_in[2];
    const int*   dst = (const int*)d_in[3];
    const float* W   = (const float*)d_in[4];
    const float* b   = (const float*)d_in[5];
    float* out = (float*)d_out;

    const int n_edges = in_sizes[2];

    zero_cnt_kernel<<<(N_DST + 1023) / 1024, 1024>>>();
    hist_kernel<<<(n_edges + 255) / 256, 256>>>(dst, n_edges);
    scan_kernel<<<1, SCAN_THREADS>>>();
    scatter_kernel<<<(n_edges + 255) / 256, 256>>>(src, dst, n_edges);
    agg_kernel<<<(N_DST * 32 + 255) / 256, 256>>>(h_s);

    int gblocks = (N_DST + BM - 1) / BM;              // 391
    gemm_kernel<<<gblocks, 256>>>(h_d, W, b, out);
}

// round 5
// speedup vs baseline: 1.3380x; 1.3380x over previous
#include <cuda_runtime.h>
#include <cstdint>

#define N_SRC 50000
#define N_DST 50000
#define IN_FEAT 128
#define OUT_FEAT 128

// Device-global scratch (allocation-free).
__device__ float g_neigh[(size_t)N_DST * IN_FEAT];
__device__ float g_deg[N_DST];

// ---------------------------------------------------------------------------
// Kernel 1: zero the accumulators
// ---------------------------------------------------------------------------
__global__ __launch_bounds__(256) void zero_kernel() {
    const size_t n4 = (size_t)N_DST * IN_FEAT / 4;
    size_t i = (size_t)blockIdx.x * blockDim.x + threadIdx.x;
    size_t stride = (size_t)gridDim.x * blockDim.x;
    float4* p = reinterpret_cast<float4*>(g_neigh);
    for (size_t j = i; j < n4; j += stride)
        p[j] = make_float4(0.f, 0.f, 0.f, 0.f);
    for (size_t j = i; j < N_DST; j += stride)
        g_deg[j] = 0.f;
}

// ---------------------------------------------------------------------------
// Kernel 2: edge aggregation. One warp per edge, vector red.add into g_neigh.
// Near the LTS roofline: 307MB gather reads + 307MB reduce writes, all L2-hit.
// ---------------------------------------------------------------------------
__global__ __launch_bounds__(256) void edge_kernel(
    const float* __restrict__ h_s,
    const int* __restrict__ src,
    const int* __restrict__ dst,
    int n_edges)
{
    int warp = (blockIdx.x * blockDim.x + threadIdx.x) >> 5;
    int lane = threadIdx.x & 31;
    if (warp >= n_edges) return;

    int s = __ldg(src + warp);
    int d = __ldg(dst + warp);

    const float4 v = __ldg(reinterpret_cast<const float4*>(h_s + (size_t)s * IN_FEAT) + lane);
    float* p = g_neigh + (size_t)d * IN_FEAT + lane * 4;
    asm volatile("red.global.add.v4.f32 [%0], {%1, %2, %3, %4};"
                 :: "l"(p), "f"(v.x), "f"(v.y), "f"(v.z), "f"(v.w)
                 : "memory");
    if (lane == 0) atomicAdd(g_deg + d, 1.0f);
}

// ---------------------------------------------------------------------------
// Kernel 3: fused mean + concat + Linear via TF32 mma.sync + ldmatrix.
//   out[d,o] = b[o] + sum_k h_d[d,k]*W[o,k] + (neigh[d,k]/max(deg,1))*W[o,128+k]
//   BM=128 x N=128, BK=32, 256 threads (8 warps as 4m x 2n), 2x8 m16n8k8/warp.
// ---------------------------------------------------------------------------
#define BM 128
#define BK 32
#define KPAD 36   // 144B row stride = 9x16B units -> LDSM rows distinct mod 8

__device__ __forceinline__ uint32_t f2tf32(float v) {
    uint32_t r;
    asm("cvt.rna.tf32.f32 %0, %1;" : "=r"(r) : "f"(v));
    return r;
}

__device__ __forceinline__ void mma_tf32(float c[4],
                                         uint32_t a0, uint32_t a1, uint32_t a2, uint32_t a3,
                                         uint32_t b0, uint32_t b1) {
    asm("mma.sync.aligned.m16n8k8.row.col.f32.tf32.tf32.f32 "
        "{%0,%1,%2,%3}, {%4,%5,%6,%7}, {%8,%9}, {%0,%1,%2,%3};"
        : "+f"(c[0]), "+f"(c[1]), "+f"(c[2]), "+f"(c[3])
        : "r"(a0), "r"(a1), "r"(a2), "r"(a3), "r"(b0), "r"(b1));
}

#define LDSM_X4(r0, r1, r2, r3, addr) \
    asm volatile("ldmatrix.sync.aligned.m8n8.x4.shared.b16 {%0,%1,%2,%3}, [%4];" \
                 : "=r"(r0), "=r"(r1), "=r"(r2), "=r"(r3) : "r"(addr))

__global__ __launch_bounds__(256) void gemm_kernel(
    const float* __restrict__ h_d,
    const float* __restrict__ W,     // [128, 256] row-major
    const float* __restrict__ bias,  // [128]
    float* __restrict__ out)         // [N_DST, 128]
{
    __shared__ uint32_t As[BM][KPAD];        // [m][k] tf32
    __shared__ uint32_t Bs[OUT_FEAT][KPAD];  // [n][k] tf32
    __shared__ float sInv[BM];

    const int t    = threadIdx.x;
    const int bm   = blockIdx.x * BM;
    const int wid  = t >> 5;
    const int lane = t & 31;
    const int warp_m = wid >> 1;   // 0..3
    const int warp_n = wid & 1;    // 0..1
    const int group  = lane >> 2;  // 0..7
    const int tid4   = lane & 3;   // 0..3

    if (t < BM) {
        int r = bm + t;
        float dg = (r < N_DST) ? g_deg[r] : 1.0f;
        sInv[t] = 1.0f / fmaxf(dg, 1.0f);
    }

    // ldmatrix per-thread row addresses
    const int lrow = lane & 7;
    const int lmat = lane >> 3;    // which 8x8 tile of the x4
    uint32_t as_base = (uint32_t)__cvta_generic_to_shared(&As[0][0]);
    uint32_t bs_base = (uint32_t)__cvta_generic_to_shared(&Bs[0][0]);

    uint32_t aAddr[2];
    #pragma unroll
    for (int mt = 0; mt < 2; ++mt) {
        int row = warp_m * 32 + mt * 16 + (lmat & 1) * 8 + lrow;
        int col = (lmat >> 1) * 4;
        aAddr[mt] = as_base + (row * KPAD + col) * 4;
    }
    uint32_t bAddr[4];
    #pragma unroll
    for (int p = 0; p < 4; ++p) {
        int row = warp_n * 64 + p * 16 + (lmat >> 1) * 8 + lrow;
        int col = (lmat & 1) * 4;
        bAddr[p] = bs_base + (row * KPAD + col) * 4;
    }

    float acc[2][8][4];
    #pragma unroll
    for (int mt = 0; mt < 2; ++mt)
        #pragma unroll
        for (int nt = 0; nt < 8; ++nt)
            #pragma unroll
            for (int c = 0; c < 4; ++c) acc[mt][nt][c] = 0.f;

    #pragma unroll 1
    for (int ph = 0; ph < 2; ++ph) {
        const float* __restrict__ A = ph ? g_neigh : h_d;
        #pragma unroll 1
        for (int k0 = 0; k0 < IN_FEAT; k0 += BK) {
            __syncthreads();   // prev compute done; sInv ready (iter 0)

            // --- A tile: 128 rows x 32 cols (1/deg folded in on phase 1)
            #pragma unroll
            for (int i = 0; i < 4; ++i) {
                int idx = t + i * 256;          // 0..1023
                int row = idx >> 3;             // 0..127
                int c4  = (idx & 7) * 4;        // 0..28
                int gr  = bm + row;
                float4 v = make_float4(0.f, 0.f, 0.f, 0.f);
                if (gr < N_DST)
                    v = __ldg(reinterpret_cast<const float4*>(A + (size_t)gr * IN_FEAT + k0 + c4));
                float s = ph ? sInv[row] : 1.0f;
                As[row][c4 + 0] = f2tf32(v.x * s);
                As[row][c4 + 1] = f2tf32(v.y * s);
                As[row][c4 + 2] = f2tf32(v.z * s);
                As[row][c4 + 3] = f2tf32(v.w * s);
            }
            // --- B tile: Bs[o][k] = W[o][ph*128 + k0 + k]
            #pragma unroll
            for (int i = 0; i < 4; ++i) {
                int idx = t + i * 256;
                int o   = idx >> 3;
                int c4  = (idx & 7) * 4;
                float4 v = __ldg(reinterpret_cast<const float4*>(
                    W + (size_t)o * (2 * IN_FEAT) + ph * IN_FEAT + k0 + c4));
                Bs[o][c4 + 0] = f2tf32(v.x);
                Bs[o][c4 + 1] = f2tf32(v.y);
                Bs[o][c4 + 2] = f2tf32(v.z);
                Bs[o][c4 + 3] = f2tf32(v.w);
            }
            __syncthreads();

            // --- compute: 4 k8-steps, fragments via LDSM.x4
            #pragma unroll
            for (int kk = 0; kk < BK; kk += 8) {
                uint32_t af[2][4], bf[8][2];
                #pragma unroll
                for (int mt = 0; mt < 2; ++mt)
                    LDSM_X4(af[mt][0], af[mt][1], af[mt][2], af[mt][3],
                            aAddr[mt] + kk * 4);
                #pragma unroll
                for (int p = 0; p < 4; ++p)
                    LDSM_X4(bf[2 * p][0], bf[2 * p][1], bf[2 * p + 1][0], bf[2 * p + 1][1],
                            bAddr[p] + kk * 4);
                #pragma unroll
                for (int mt = 0; mt < 2; ++mt)
                    #pragma unroll
                    for (int nt = 0; nt < 8; ++nt)
                        mma_tf32(acc[mt][nt], af[mt][0], af[mt][1], af[mt][2], af[mt][3],
                                 bf[nt][0], bf[nt][1]);
            }
        }
    }

    // --- epilogue: bias + store
    #pragma unroll
    for (int mt = 0; mt < 2; ++mt) {
        int r0 = bm + warp_m * 32 + mt * 16 + group;
        #pragma unroll
        for (int nt = 0; nt < 8; ++nt) {
            int c = warp_n * 64 + nt * 8 + tid4 * 2;
            float b0 = __ldg(bias + c);
            float b1 = __ldg(bias + c + 1);
            if (r0 < N_DST) {
                float2 v = make_float2(acc[mt][nt][0] + b0, acc[mt][nt][1] + b1);
                *reinterpret_cast<float2*>(out + (size_t)r0 * OUT_FEAT + c) = v;
            }
            int r1 = r0 + 8;
            if (r1 < N_DST) {
                float2 v = make_float2(acc[mt][nt][2] + b0, acc[mt][nt][3] + b1);
                *reinterpret_cast<float2*>(out + (size_t)r1 * OUT_FEAT + c) = v;
            }
        }
    }
}

// ---------------------------------------------------------------------------
extern "C" void kernel_launch(void* const* d_in, const int* in_sizes, int n_in,
                              void* d_out, int out_size)
{
    const float* h_s = (const float*)d_in[0];
    const float* h_d = (const float*)d_in[1];
    const int*   src = (const int*)d_in[2];
    const int*   dst = (const int*)d_in[3];
    const float* W   = (const float*)d_in[4];
    const float* b   = (const float*)d_in[5];
    float* out = (float*)d_out;

    const int n_edges = in_sizes[2];

    zero_kernel<<<2960, 256>>>();

    int blocks = (n_edges * 32 + 255) / 256;
    edge_kernel<<<blocks, 256>>>(h_s, src, dst, n_edges);

    int gblocks = (N_DST + BM - 1) / BM;              // 391
    gemm_kernel<<<gblocks, 256>>>(h_d, W, b, out);
}